// round 5
// baseline (speedup 1.0000x reference)
#include <cuda_runtime.h>
#include <math.h>

// Problem constants (fixed by the dataset): N=200000, D=128, E=500000, NUM_REL=200, B=256
#define MAX_N   200000
#define MAX_REL 256
#define MAX_B   256

// Scratch (allocation-free rule: __device__ globals)
__device__ float g_s0[MAX_N];   // node[n] . W[0:128]
__device__ float g_s1[MAX_N];   // node[n] . W[128:256]
__device__ float g_s3[MAX_N];   // node[n] . W[384:512]
__device__ float g_r2[MAX_REL]; // R[r]    . W[256:384]
__device__ float g_r4[MAX_REL]; // R[r]    . W[512:640]
__device__ float g_c [MAX_B];   // s3[h_index[b]] + r4[r_index[b]]

// ---------------------------------------------------------------------------
// Kernel 1: per-node partial dots (streams node_embeds once: 102.4 MB).
// Four nodes per warp: four independent float4 loads front-batched
// (MLP_p1=4 — knee of the B300 DRAM-latency/MLP model; PTW fully hidden).
// Each node's row is one fully-coalesced 512B warp transaction.
// ---------------------------------------------------------------------------
__global__ void node_sums_kernel(const float* __restrict__ node,
                                 const float* __restrict__ W, int N) {
    int warp = (blockIdx.x * blockDim.x + threadIdx.x) >> 5;
    int lane = threadIdx.x & 31;
    int n0 = warp * 4;
    if (n0 >= N) return;

    const float4* np = reinterpret_cast<const float4*>(node);
    const float4* wp = reinterpret_cast<const float4*>(W);

    float4 v[4];
    const float4 z = make_float4(0.f, 0.f, 0.f, 0.f);
#pragma unroll
    for (int i = 0; i < 4; i++)
        v[i] = (n0 + i < N) ? __ldg(np + (size_t)(n0 + i) * 32 + lane) : z;

    float4 w0 = __ldg(wp + 0 * 32 + lane);
    float4 w1 = __ldg(wp + 1 * 32 + lane);
    float4 w3 = __ldg(wp + 3 * 32 + lane);

    float s0[4], s1[4], s3[4];
#pragma unroll
    for (int i = 0; i < 4; i++) {
        s0[i] = v[i].x * w0.x + v[i].y * w0.y + v[i].z * w0.z + v[i].w * w0.w;
        s1[i] = v[i].x * w1.x + v[i].y * w1.y + v[i].z * w1.z + v[i].w * w1.w;
        s3[i] = v[i].x * w3.x + v[i].y * w3.y + v[i].z * w3.z + v[i].w * w3.w;
    }

#pragma unroll
    for (int off = 16; off; off >>= 1) {
#pragma unroll
        for (int i = 0; i < 4; i++) {
            s0[i] += __shfl_xor_sync(0xffffffffu, s0[i], off);
            s1[i] += __shfl_xor_sync(0xffffffffu, s1[i], off);
            s3[i] += __shfl_xor_sync(0xffffffffu, s3[i], off);
        }
    }
    if (lane == 0) {
#pragma unroll
        for (int i = 0; i < 4; i++) {
            if (n0 + i < N) {
                g_s0[n0 + i] = s0[i];
                g_s1[n0 + i] = s1[i];
                g_s3[n0 + i] = s3[i];
            }
        }
    }
}

// ---------------------------------------------------------------------------
// Kernel 2: per-relation partial dots (200 rows — trivial)
// ---------------------------------------------------------------------------
__global__ void rel_sums_kernel(const float* __restrict__ R,
                                const float* __restrict__ W, int NUM_REL) {
    int warp = (blockIdx.x * blockDim.x + threadIdx.x) >> 5;
    int lane = threadIdx.x & 31;
    if (warp >= NUM_REL) return;

    float4 v  = __ldg(reinterpret_cast<const float4*>(R) + warp * 32 + lane);
    float4 w2 = __ldg(reinterpret_cast<const float4*>(W) + 2 * 32 + lane);
    float4 w4 = __ldg(reinterpret_cast<const float4*>(W) + 4 * 32 + lane);

    float s2 = v.x * w2.x + v.y * w2.y + v.z * w2.z + v.w * w2.w;
    float s4 = v.x * w4.x + v.y * w4.y + v.z * w4.z + v.w * w4.w;

#pragma unroll
    for (int off = 16; off; off >>= 1) {
        s2 += __shfl_xor_sync(0xffffffffu, s2, off);
        s4 += __shfl_xor_sync(0xffffffffu, s4, off);
    }
    if (lane == 0) {
        g_r2[warp] = s2;
        g_r4[warp] = s4;
    }
}

// ---------------------------------------------------------------------------
// Kernel 3: per-batch constant c[b] = s3[h_index[b]] + r4[r_index[b]]
// ---------------------------------------------------------------------------
__global__ void batch_c_kernel(const int* __restrict__ h_index,
                               const int* __restrict__ r_index, int B) {
    int b = blockIdx.x * blockDim.x + threadIdx.x;
    if (b < B) g_c[b] = g_s3[h_index[b]] + g_r4[r_index[b]];
}

// ---------------------------------------------------------------------------
// Kernel 4: per-edge gather + gumbel-sigmoid gate (grid-stride, fixed grid)
// sw = s0[row] + s1[col] + r2[etype] + c[bid] + b
// eps = (2*BIAS-1)*u + (1-BIAS);  out = sigmoid((log(eps)-log1p(-eps)+sw)/TEMP)
// ---------------------------------------------------------------------------
__global__ void edge_kernel(const int*   __restrict__ ei,     // (2,E) row-major
                            const int*   __restrict__ et,
                            const int*   __restrict__ bid,
                            const float* __restrict__ eps_u,
                            const float* __restrict__ bptr,
                            float*       __restrict__ out,
                            int E) {
    float bias = __ldg(bptr);
    int stride = gridDim.x * blockDim.x;
    for (int e = blockIdx.x * blockDim.x + threadIdx.x; e < E; e += stride) {
        int   row = __ldg(ei + e);
        int   col = __ldg(ei + E + e);
        int   t   = __ldg(et + e);
        int   b   = __ldg(bid + e);
        float u   = __ldg(eps_u + e);

        float sw  = __ldg(&g_s0[row]) + __ldg(&g_s1[col]) + __ldg(&g_r2[t])
                  + __ldg(&g_c[b]) + bias;
        // eps = (2*1e-4 - 1)*u + (1 - 1e-4)
        float eps  = fmaf(-0.9998f, u, 0.9999f);
        float gate = (__logf(eps) - log1pf(-eps) + sw) * 0.2f;   // /TEMP, TEMP=5
        out[e] = 1.0f / (1.0f + __expf(-gate));
    }
}

extern "C" void kernel_launch(void* const* d_in, const int* in_sizes, int n_in,
                              void* d_out, int out_size) {
    const float* node    = (const float*)d_in[0];
    const float* R       = (const float*)d_in[1];
    const float* W       = (const float*)d_in[2];
    const float* bptr    = (const float*)d_in[3];
    const float* eps_u   = (const float*)d_in[4];
    const int*   ei      = (const int*)d_in[5];
    const int*   et      = (const int*)d_in[6];
    const int*   bid     = (const int*)d_in[7];
    const int*   h_index = (const int*)d_in[8];
    const int*   r_index = (const int*)d_in[9];
    float*       out     = (float*)d_out;

    int D       = in_sizes[2] / 5;       // 128
    int N       = in_sizes[0] / D;       // 200000
    int NUM_REL = in_sizes[1] / D;       // 200
    int E       = in_sizes[4];           // 500000
    int B       = in_sizes[8];           // 256

    // k2 first (tiny, independent)
    {
        int blocks = (NUM_REL * 32 + 255) / 256;
        rel_sums_kernel<<<blocks, 256>>>(R, W, NUM_REL);
    }
    // k1: node partial sums (dominant — streams node_embeds once)
    {
        int warps  = (N + 3) / 4;                 // four nodes per warp
        int blocks = (warps * 32 + 255) / 256;
        node_sums_kernel<<<blocks, 256>>>(node, W, N);
    }
    // k3: per-batch constants (needs k1 + k2; stream order enforces it)
    batch_c_kernel<<<(B + 255) / 256, 256>>>(h_index, r_index, B);

    // k4: per-edge output — fixed grid, grid-stride for balanced waves
    edge_kernel<<<148 * 16, 256>>>(ei, et, bid, eps_u, bptr, out, E);
}

// round 6
// speedup vs baseline: 1.0284x; 1.0284x over previous
#include <cuda_runtime.h>
#include <math.h>

// Problem constants (fixed by the dataset): N=200000, D=128, E=500000, NUM_REL=200, B=256
#define MAX_N   200000
#define MAX_REL 256
#define MAX_B   256

// Scratch (allocation-free rule: __device__ globals)
__device__ float g_s0[MAX_N];   // node[n] . W[0:128]
__device__ float g_s1[MAX_N];   // node[n] . W[128:256]
__device__ float g_s3[MAX_N];   // node[n] . W[384:512]
__device__ float g_r2[MAX_REL]; // R[r]    . W[256:384]
__device__ float g_r4[MAX_REL]; // R[r]    . W[512:640]
__device__ float g_c [MAX_B];   // s3[h_index[b]] + r4[r_index[b]]

// ---------------------------------------------------------------------------
// Kernel 1: per-node partial dots (streams node_embeds once: 102.4 MB).
// EIGHT nodes per warp: 8 independent float4 loads front-batched (MLP_p1=8).
// Each node's row is one fully-coalesced 512B warp transaction.
// ---------------------------------------------------------------------------
#define NODES_PER_WARP 8
__global__ void node_sums_kernel(const float* __restrict__ node,
                                 const float* __restrict__ W, int N) {
    int warp = (blockIdx.x * blockDim.x + threadIdx.x) >> 5;
    int lane = threadIdx.x & 31;
    int n0 = warp * NODES_PER_WARP;
    if (n0 >= N) return;

    const float4* np = reinterpret_cast<const float4*>(node);
    const float4* wp = reinterpret_cast<const float4*>(W);

    float4 v[NODES_PER_WARP];
    const float4 z = make_float4(0.f, 0.f, 0.f, 0.f);
#pragma unroll
    for (int i = 0; i < NODES_PER_WARP; i++)
        v[i] = (n0 + i < N) ? __ldg(np + (size_t)(n0 + i) * 32 + lane) : z;

    float4 w0 = __ldg(wp + 0 * 32 + lane);
    float4 w1 = __ldg(wp + 1 * 32 + lane);
    float4 w3 = __ldg(wp + 3 * 32 + lane);

    float s0[NODES_PER_WARP], s1[NODES_PER_WARP], s3[NODES_PER_WARP];
#pragma unroll
    for (int i = 0; i < NODES_PER_WARP; i++) {
        s0[i] = v[i].x * w0.x + v[i].y * w0.y + v[i].z * w0.z + v[i].w * w0.w;
        s1[i] = v[i].x * w1.x + v[i].y * w1.y + v[i].z * w1.z + v[i].w * w1.w;
        s3[i] = v[i].x * w3.x + v[i].y * w3.y + v[i].z * w3.z + v[i].w * w3.w;
    }

#pragma unroll
    for (int off = 16; off; off >>= 1) {
#pragma unroll
        for (int i = 0; i < NODES_PER_WARP; i++) {
            s0[i] += __shfl_xor_sync(0xffffffffu, s0[i], off);
            s1[i] += __shfl_xor_sync(0xffffffffu, s1[i], off);
            s3[i] += __shfl_xor_sync(0xffffffffu, s3[i], off);
        }
    }
    if (lane == 0) {
#pragma unroll
        for (int i = 0; i < NODES_PER_WARP; i++) {
            if (n0 + i < N) {
                g_s0[n0 + i] = s0[i];
                g_s1[n0 + i] = s1[i];
                g_s3[n0 + i] = s3[i];
            }
        }
    }
}

// ---------------------------------------------------------------------------
// Kernel 2: per-relation partial dots (200 rows — trivial)
// ---------------------------------------------------------------------------
__global__ void rel_sums_kernel(const float* __restrict__ R,
                                const float* __restrict__ W, int NUM_REL) {
    int warp = (blockIdx.x * blockDim.x + threadIdx.x) >> 5;
    int lane = threadIdx.x & 31;
    if (warp >= NUM_REL) return;

    float4 v  = __ldg(reinterpret_cast<const float4*>(R) + warp * 32 + lane);
    float4 w2 = __ldg(reinterpret_cast<const float4*>(W) + 2 * 32 + lane);
    float4 w4 = __ldg(reinterpret_cast<const float4*>(W) + 4 * 32 + lane);

    float s2 = v.x * w2.x + v.y * w2.y + v.z * w2.z + v.w * w2.w;
    float s4 = v.x * w4.x + v.y * w4.y + v.z * w4.z + v.w * w4.w;

#pragma unroll
    for (int off = 16; off; off >>= 1) {
        s2 += __shfl_xor_sync(0xffffffffu, s2, off);
        s4 += __shfl_xor_sync(0xffffffffu, s4, off);
    }
    if (lane == 0) {
        g_r2[warp] = s2;
        g_r4[warp] = s4;
    }
}

// ---------------------------------------------------------------------------
// Kernel 3: per-batch constant c[b] = s3[h_index[b]] + r4[r_index[b]]
// ---------------------------------------------------------------------------
__global__ void batch_c_kernel(const int* __restrict__ h_index,
                               const int* __restrict__ r_index, int B) {
    int b = blockIdx.x * blockDim.x + threadIdx.x;
    if (b < B) g_c[b] = g_s3[h_index[b]] + g_r4[r_index[b]];
}

// ---------------------------------------------------------------------------
// Kernel 4: per-edge gather + gumbel-sigmoid gate.
// FOUR edges per thread, vectorized: 5 front-batched vector loads (int4 x4 +
// float4), then 16 independent scalar gathers (L2-resident tables), then one
// float4 store. Per-thread MLP ~21 vs ~5 before — attacks the
// stall_long_scoreboard / issue=16.9% profile from round 5.
// ---------------------------------------------------------------------------
__global__ void edge_kernel4(const int*   __restrict__ ei,     // (2,E) row-major
                             const int*   __restrict__ et,
                             const int*   __restrict__ bid,
                             const float* __restrict__ eps_u,
                             const float* __restrict__ bptr,
                             float*       __restrict__ out,
                             int E) {
    int tid = blockIdx.x * blockDim.x + threadIdx.x;
    int e0  = tid * 4;
    if (e0 >= E) return;
    float bias = __ldg(bptr);

    if (e0 + 3 < E) {
        // Front-batched vector loads (fully coalesced: 16B/lane)
        int4   rows = __ldg(reinterpret_cast<const int4*>(ei) + tid);
        int4   cols = __ldg(reinterpret_cast<const int4*>(ei + E) + tid);
        int4   ts   = __ldg(reinterpret_cast<const int4*>(et) + tid);
        int4   bs   = __ldg(reinterpret_cast<const int4*>(bid) + tid);
        float4 us   = __ldg(reinterpret_cast<const float4*>(eps_u) + tid);

        int ra[4] = {rows.x, rows.y, rows.z, rows.w};
        int ca[4] = {cols.x, cols.y, cols.z, cols.w};
        int ta[4] = {ts.x, ts.y, ts.z, ts.w};
        int ba[4] = {bs.x, bs.y, bs.z, bs.w};
        float ua[4] = {us.x, us.y, us.z, us.w};

        // Independent gathers — issue all before consuming
        float a0[4], a1[4], a2[4], ac[4];
#pragma unroll
        for (int i = 0; i < 4; i++) a0[i] = __ldg(&g_s0[ra[i]]);
#pragma unroll
        for (int i = 0; i < 4; i++) a1[i] = __ldg(&g_s1[ca[i]]);
#pragma unroll
        for (int i = 0; i < 4; i++) a2[i] = __ldg(&g_r2[ta[i]]);
#pragma unroll
        for (int i = 0; i < 4; i++) ac[i] = __ldg(&g_c[ba[i]]);

        float4 res;
        float* rp = &res.x;
#pragma unroll
        for (int i = 0; i < 4; i++) {
            float sw   = a0[i] + a1[i] + a2[i] + ac[i] + bias;
            float eps  = fmaf(-0.9998f, ua[i], 0.9999f);
            float gate = (__logf(eps) - log1pf(-eps) + sw) * 0.2f;   // /TEMP
            rp[i] = 1.0f / (1.0f + __expf(-gate));
        }
        reinterpret_cast<float4*>(out)[tid] = res;
    } else {
        // Tail (E not multiple of 4)
        for (int e = e0; e < E; e++) {
            int   row = __ldg(ei + e);
            int   col = __ldg(ei + E + e);
            int   t   = __ldg(et + e);
            int   b   = __ldg(bid + e);
            float u   = __ldg(eps_u + e);
            float sw   = __ldg(&g_s0[row]) + __ldg(&g_s1[col]) + __ldg(&g_r2[t])
                       + __ldg(&g_c[b]) + bias;
            float eps  = fmaf(-0.9998f, u, 0.9999f);
            float gate = (__logf(eps) - log1pf(-eps) + sw) * 0.2f;
            out[e] = 1.0f / (1.0f + __expf(-gate));
        }
    }
}

extern "C" void kernel_launch(void* const* d_in, const int* in_sizes, int n_in,
                              void* d_out, int out_size) {
    const float* node    = (const float*)d_in[0];
    const float* R       = (const float*)d_in[1];
    const float* W       = (const float*)d_in[2];
    const float* bptr    = (const float*)d_in[3];
    const float* eps_u   = (const float*)d_in[4];
    const int*   ei      = (const int*)d_in[5];
    const int*   et      = (const int*)d_in[6];
    const int*   bid     = (const int*)d_in[7];
    const int*   h_index = (const int*)d_in[8];
    const int*   r_index = (const int*)d_in[9];
    float*       out     = (float*)d_out;

    int D       = in_sizes[2] / 5;       // 128
    int N       = in_sizes[0] / D;       // 200000
    int NUM_REL = in_sizes[1] / D;       // 200
    int E       = in_sizes[4];           // 500000
    int B       = in_sizes[8];           // 256

    // k2 first (tiny, independent)
    {
        int blocks = (NUM_REL * 32 + 255) / 256;
        rel_sums_kernel<<<blocks, 256>>>(R, W, NUM_REL);
    }
    // k1: node partial sums (dominant — streams node_embeds once)
    {
        int warps  = (N + NODES_PER_WARP - 1) / NODES_PER_WARP;
        int blocks = (warps * 32 + 255) / 256;
        node_sums_kernel<<<blocks, 256>>>(node, W, N);
    }
    // k3: per-batch constants (needs k1 + k2; stream order enforces it)
    batch_c_kernel<<<(B + 255) / 256, 256>>>(h_index, r_index, B);

    // k4: per-edge output, 4 edges per thread
    {
        int threads = (E + 3) / 4;
        int blocks  = (threads + 255) / 256;
        edge_kernel4<<<blocks, 256>>>(ei, et, bid, eps_u, bptr, out, E);
    }
}

// round 7
// speedup vs baseline: 1.1467x; 1.1150x over previous
#include <cuda_runtime.h>
#include <math.h>

// Problem constants (fixed by the dataset): N=200000, D=128, E=500000, NUM_REL=200, B=256
#define MAX_N   200000
#define MAX_REL 256
#define MAX_B   256
#define NODES_PER_WARP 8

// Scratch (allocation-free rule: __device__ globals)
__device__ float g_s0[MAX_N];   // node[n] . W[0:128]
__device__ float g_s1[MAX_N];   // node[n] . W[128:256]
__device__ float g_s3[MAX_N];   // node[n] . W[384:512]
__device__ float g_r2[MAX_REL]; // R[r]    . W[256:384]
__device__ float g_r4[MAX_REL]; // R[r]    . W[512:640]
__device__ float g_c [MAX_B];   // s3[h_index[b]] + r4[r_index[b]]

// ---------------------------------------------------------------------------
// Kernel 1: per-node partial dots (streams node_embeds once: 102.4 MB) with
// relation sums fused in (first NUM_REL warps also reduce R rows).
// Eight nodes per warp, loads front-batched, no bounds checks (N % 8 == 0).
// ---------------------------------------------------------------------------
__global__ void node_rel_sums_kernel(const float* __restrict__ node,
                                     const float* __restrict__ R,
                                     const float* __restrict__ W,
                                     int N, int NUM_REL) {
    int warp = (blockIdx.x * blockDim.x + threadIdx.x) >> 5;
    int lane = threadIdx.x & 31;
    int n0 = warp * NODES_PER_WARP;
    if (n0 >= N) return;

    const float4* np = reinterpret_cast<const float4*>(node);
    const float4* wp = reinterpret_cast<const float4*>(W);

    float4 v[NODES_PER_WARP];
#pragma unroll
    for (int i = 0; i < NODES_PER_WARP; i++)
        v[i] = __ldg(np + (size_t)(n0 + i) * 32 + lane);

    float4 w0 = __ldg(wp + 0 * 32 + lane);
    float4 w1 = __ldg(wp + 1 * 32 + lane);
    float4 w3 = __ldg(wp + 3 * 32 + lane);

    float s0[NODES_PER_WARP], s1[NODES_PER_WARP], s3[NODES_PER_WARP];
#pragma unroll
    for (int i = 0; i < NODES_PER_WARP; i++) {
        s0[i] = v[i].x * w0.x + v[i].y * w0.y + v[i].z * w0.z + v[i].w * w0.w;
        s1[i] = v[i].x * w1.x + v[i].y * w1.y + v[i].z * w1.z + v[i].w * w1.w;
        s3[i] = v[i].x * w3.x + v[i].y * w3.y + v[i].z * w3.z + v[i].w * w3.w;
    }

#pragma unroll
    for (int off = 16; off; off >>= 1) {
#pragma unroll
        for (int i = 0; i < NODES_PER_WARP; i++) {
            s0[i] += __shfl_xor_sync(0xffffffffu, s0[i], off);
            s1[i] += __shfl_xor_sync(0xffffffffu, s1[i], off);
            s3[i] += __shfl_xor_sync(0xffffffffu, s3[i], off);
        }
    }
    if (lane == 0) {
#pragma unroll
        for (int i = 0; i < NODES_PER_WARP; i++) {
            g_s0[n0 + i] = s0[i];
            g_s1[n0 + i] = s1[i];
            g_s3[n0 + i] = s3[i];
        }
    }

    // Fused relation sums: warp w < NUM_REL also reduces R[w]
    if (warp < NUM_REL) {
        float4 rv = __ldg(reinterpret_cast<const float4*>(R) + warp * 32 + lane);
        float4 w2 = __ldg(wp + 2 * 32 + lane);
        float4 w4 = __ldg(wp + 4 * 32 + lane);
        float s2 = rv.x * w2.x + rv.y * w2.y + rv.z * w2.z + rv.w * w2.w;
        float s4 = rv.x * w4.x + rv.y * w4.y + rv.z * w4.z + rv.w * w4.w;
#pragma unroll
        for (int off = 16; off; off >>= 1) {
            s2 += __shfl_xor_sync(0xffffffffu, s2, off);
            s4 += __shfl_xor_sync(0xffffffffu, s4, off);
        }
        if (lane == 0) { g_r2[warp] = s2; g_r4[warp] = s4; }
    }
}

// ---------------------------------------------------------------------------
// Kernel 2: per-batch constant c[b] = s3[h_index[b]] + r4[r_index[b]]
// ---------------------------------------------------------------------------
__global__ void batch_c_kernel(const int* __restrict__ h_index,
                               const int* __restrict__ r_index, int B) {
    int b = blockIdx.x * blockDim.x + threadIdx.x;
    if (b < B) g_c[b] = g_s3[h_index[b]] + g_r4[r_index[b]];
}

// ---------------------------------------------------------------------------
// Kernel 3: per-edge gather + gumbel-sigmoid gate.
// TWO edges per thread (occupancy ~2x round-6) with the small tables (r2, c)
// staged in shared memory — random-over-200 gathers cost ~4 cyc via the smem
// crossbar instead of ~23 L1tex wavefronts. Only the two truly-scattered
// node-table gathers (s0[row], s1[col]) remain in L1tex/L2.
// ---------------------------------------------------------------------------
__global__ void edge_kernel2(const int*   __restrict__ ei,     // (2,E) row-major
                             const int*   __restrict__ et,
                             const int*   __restrict__ bid,
                             const float* __restrict__ eps_u,
                             const float* __restrict__ bptr,
                             float*       __restrict__ out,
                             int E, int NUM_REL, int B) {
    __shared__ float s_r2[MAX_REL];
    __shared__ float s_c [MAX_B];
    int t = threadIdx.x;
    if (t < MAX_REL) s_r2[t] = (t < NUM_REL) ? g_r2[t] : 0.0f;
    if (t < MAX_B)   s_c[t]  = (t < B)       ? g_c[t]  : 0.0f;
    __syncthreads();

    int tid = blockIdx.x * blockDim.x + t;
    int e0  = tid * 2;
    if (e0 >= E) return;
    float bias = __ldg(bptr);

    if (e0 + 1 < E) {
        int2   rows = __ldg(reinterpret_cast<const int2*>(ei) + tid);
        int2   cols = __ldg(reinterpret_cast<const int2*>(ei + E) + tid);
        int2   ts   = __ldg(reinterpret_cast<const int2*>(et) + tid);
        int2   bs   = __ldg(reinterpret_cast<const int2*>(bid) + tid);
        float2 us   = __ldg(reinterpret_cast<const float2*>(eps_u) + tid);

        // Scattered gathers, front-batched
        float a0x = __ldg(&g_s0[rows.x]);
        float a0y = __ldg(&g_s0[rows.y]);
        float a1x = __ldg(&g_s1[cols.x]);
        float a1y = __ldg(&g_s1[cols.y]);
        // smem tables
        float r2x = s_r2[ts.x], r2y = s_r2[ts.y];
        float cx  = s_c[bs.x],  cy  = s_c[bs.y];

        float swx = a0x + a1x + r2x + cx + bias;
        float swy = a0y + a1y + r2y + cy + bias;

        float ex = fmaf(-0.9998f, us.x, 0.9999f);
        float ey = fmaf(-0.9998f, us.y, 0.9999f);
        float gx = (__logf(ex) - log1pf(-ex) + swx) * 0.2f;
        float gy = (__logf(ey) - log1pf(-ey) + swy) * 0.2f;

        float2 res;
        res.x = 1.0f / (1.0f + __expf(-gx));
        res.y = 1.0f / (1.0f + __expf(-gy));
        reinterpret_cast<float2*>(out)[tid] = res;
    } else {
        int e = e0;
        int   row = __ldg(ei + e);
        int   col = __ldg(ei + E + e);
        int   tt  = __ldg(et + e);
        int   b   = __ldg(bid + e);
        float u   = __ldg(eps_u + e);
        float sw  = __ldg(&g_s0[row]) + __ldg(&g_s1[col]) + s_r2[tt] + s_c[b] + bias;
        float eps  = fmaf(-0.9998f, u, 0.9999f);
        float gate = (__logf(eps) - log1pf(-eps) + sw) * 0.2f;
        out[e] = 1.0f / (1.0f + __expf(-gate));
    }
}

extern "C" void kernel_launch(void* const* d_in, const int* in_sizes, int n_in,
                              void* d_out, int out_size) {
    const float* node    = (const float*)d_in[0];
    const float* R       = (const float*)d_in[1];
    const float* W       = (const float*)d_in[2];
    const float* bptr    = (const float*)d_in[3];
    const float* eps_u   = (const float*)d_in[4];
    const int*   ei      = (const int*)d_in[5];
    const int*   et      = (const int*)d_in[6];
    const int*   bid     = (const int*)d_in[7];
    const int*   h_index = (const int*)d_in[8];
    const int*   r_index = (const int*)d_in[9];
    float*       out     = (float*)d_out;

    int D       = in_sizes[2] / 5;       // 128
    int N       = in_sizes[0] / D;       // 200000
    int NUM_REL = in_sizes[1] / D;       // 200
    int E       = in_sizes[4];           // 500000
    int B       = in_sizes[8];           // 256

    // k1: node partial sums + fused relation sums
    {
        int warps  = (N + NODES_PER_WARP - 1) / NODES_PER_WARP;  // 25000 (exact)
        int blocks = (warps * 32 + 255) / 256;
        node_rel_sums_kernel<<<blocks, 256>>>(node, R, W, N, NUM_REL);
    }
    // k2: per-batch constants (needs k1; stream order enforces it)
    batch_c_kernel<<<(B + 255) / 256, 256>>>(h_index, r_index, B);

    // k3: per-edge output, 2 edges per thread, smem tables
    {
        int threads = (E + 1) / 2;
        int blocks  = (threads + 255) / 256;
        edge_kernel2<<<blocks, 256>>>(ei, et, bid, eps_u, bptr, out, E, NUM_REL, B);
    }
}